// round 17
// baseline (speedup 1.0000x reference)
#include <cuda_runtime.h>
#include <cuda_fp16.h>
#include <cstdint>

// out[i][j] = -sqrt(max(||f_i||^2 + ||f_j||^2 - 2 f_i.f_j, 0)),  f: [8192,512] fp32
// fp16 mma.sync m16n8k16 syrk, upper-triangular CTA tiles + mirrored write.
// CTA tile 128x128, 4 warps (2x2), warp tile 64x64, BK=64, 3-stage cp.async
// pipeline, 2 CTAs/SM. FINE-GRAINED INTERLEAVE: each k16 sub-step's 8 ldmatrix
// are threaded 1-per-4-MMAs through the previous sub-step's 32 MMAs, so the
// HMMA stream never pauses for load bursts. Cross-kt barrier+prefetch kept.
// Exact fp32 norms; shuffle-vectorized STG.128 + sqrt.approx epilogue. Diag=0.

#define NROWS 8192
#define DDIM  512

#define TM 128
#define TN 128
#define BK 64
#define LDSZ 72                    // 64 + 8 fp16 pad -> 144B row stride, conflict-free
#define STAGES 3
#define NKT (DDIM / BK)            // 8
#define NT (NROWS / TM)            // 64
#define NSTRICT (NT * (NT - 1) / 2)   // 2016
#define NTILES (NSTRICT + NT)         // 2080

#define A_ELE (TM * LDSZ)          // 9216 fp16 per stage
#define B_ELE (TN * LDSZ)
#define PIPE_BYTES (STAGES * (A_ELE + B_ELE) * 2)    // 110592 B
#define STG_S 132                  // transposed-stage stride (floats)
#define SMEM_BYTES (PIPE_BYTES + TN * 4)

__device__ __half g_fb[NROWS * DDIM];
__device__ float g_norms[NROWS];

__device__ __forceinline__ float nsqrt_approx(float x) {
    float r;
    asm("sqrt.approx.f32 %0, %1;" : "=f"(r) : "f"(x));
    return -r;
}

// ---------------------------------------------------------------------------
__global__ __launch_bounds__(512)
void prep_kernel(const float* __restrict__ f) {
    const int lane = threadIdx.x & 31;
    const int row  = blockIdx.x * 16 + (threadIdx.x >> 5);
    const float* src = f + (size_t)row * DDIM;
    __half* dst = g_fb + (size_t)row * DDIM;

    float s = 0.f;
#pragma unroll
    for (int half = 0; half < 2; half++) {
        const float4 v0 = *(const float4*)(src + half * 256 + lane * 8);
        const float4 v1 = *(const float4*)(src + half * 256 + lane * 8 + 4);
        s += v0.x * v0.x + v0.y * v0.y + v0.z * v0.z + v0.w * v0.w;
        s += v1.x * v1.x + v1.y * v1.y + v1.z * v1.z + v1.w * v1.w;
        __half2 p0 = __float22half2_rn(make_float2(v0.x, v0.y));
        __half2 p1 = __float22half2_rn(make_float2(v0.z, v0.w));
        __half2 p2 = __float22half2_rn(make_float2(v1.x, v1.y));
        __half2 p3 = __float22half2_rn(make_float2(v1.z, v1.w));
        uint4 pk;
        pk.x = *(uint32_t*)&p0; pk.y = *(uint32_t*)&p1;
        pk.z = *(uint32_t*)&p2; pk.w = *(uint32_t*)&p3;
        *(uint4*)(dst + half * 256 + lane * 8) = pk;
    }
#pragma unroll
    for (int o = 16; o; o >>= 1) s += __shfl_xor_sync(0xffffffffu, s, o);
    if (lane == 0) g_norms[row] = s;
}

// ---------------------------------------------------------------------------
__device__ __forceinline__ int s_off(int x) { return x * (2 * NT - 1 - x) / 2; }

__global__ __launch_bounds__(128, 2)
void gemm_kernel(float* __restrict__ out) {
    extern __shared__ __half sm[];
    __half* As = sm;                     // [STAGES][TM][LDSZ]
    __half* Bs = sm + STAGES * A_ELE;    // [STAGES][TN][LDSZ]
    float* nb_s = reinterpret_cast<float*>(sm + STAGES * (A_ELE + B_ELE)); // [TN]
    float* staged = reinterpret_cast<float*>(sm);       // [TN][STG_S] (reuses pipe)

    const int tid  = threadIdx.x;
    const int lane = tid & 31;
    const int warp = tid >> 5;
    const int wm = warp >> 1;
    const int wn = warp & 1;

    // tile decode: strictly-upper first, diagonal last
    const int t = blockIdx.x;
    int bi, bj;
    if (t < NSTRICT) {
        bi = (int)(((2.f * NT - 1.f) -
                    sqrtf((2.f * NT - 1.f) * (2.f * NT - 1.f) - 8.f * (float)t)) * 0.5f);
        while (bi > 0 && s_off(bi) > t) bi--;
        while (s_off(bi + 1) <= t) bi++;
        bj = bi + 1 + (t - s_off(bi));
    } else {
        bi = bj = t - NSTRICT;
    }

    const int rowA0 = bi * TM;
    const int rowB0 = bj * TN;

    if (tid < TN) nb_s[tid] = g_norms[rowB0 + tid];

    // fp16 accumulators: 2 u32 (4 half) per (mt,nt)
    uint32_t acc[4][8][2];
#pragma unroll
    for (int i = 0; i < 4; i++)
#pragma unroll
        for (int j = 0; j < 8; j++) {
            acc[i][j][0] = 0u;
            acc[i][j][1] = 0u;
        }

    const int a_row = wm * 64 + (lane & 7) + ((lane >> 3) & 1) * 8;  // + mt*16
    const int a_kk  = (lane >> 4) * 8;                               // + ks*16
    const int b_row = wn * 64 + (lane & 7) + (lane >> 4) * 8;        // + p*16
    const int b_kk  = ((lane >> 3) & 1) * 8;                         // + ks*16

    uint32_t a[2][4][4];
    uint32_t b[2][8][2];

#define ISSUE(kt_, s_)                                                                        \
    do {                                                                                      \
        const int k0_ = (kt_) * BK;                                                           \
        __half* as_ = As + (s_) * A_ELE;                                                      \
        __half* bs_ = Bs + (s_) * B_ELE;                                                      \
        _Pragma("unroll")                                                                     \
        for (int i_ = 0; i_ < 8; i_++) {                                                      \
            int idx_ = tid + i_ * 128;                                                        \
            int r_   = idx_ >> 3;                                                             \
            int c_   = (idx_ & 7) << 3;                                                       \
            uint32_t da_ = (uint32_t)__cvta_generic_to_shared(as_ + r_ * LDSZ + c_);          \
            const __half* ga_ = g_fb + (size_t)(rowA0 + r_) * DDIM + k0_ + c_;                \
            asm volatile("cp.async.cg.shared.global [%0], [%1], 16;\n" :: "r"(da_), "l"(ga_));\
            uint32_t db_ = (uint32_t)__cvta_generic_to_shared(bs_ + r_ * LDSZ + c_);          \
            const __half* gb_ = g_fb + (size_t)(rowB0 + r_) * DDIM + k0_ + c_;                \
            asm volatile("cp.async.cg.shared.global [%0], [%1], 16;\n" :: "r"(db_), "l"(gb_));\
        }                                                                                     \
        asm volatile("cp.async.commit_group;\n" ::: "memory");                                \
    } while (0)

    // single ldmatrix: A fragment mt_ of sub-step ks_ into buffer fb_
#define LDSM_A(as_, ks_, fb_, mt_)                                                            \
    do {                                                                                      \
        uint32_t ad_ = (uint32_t)__cvta_generic_to_shared(                                    \
            (as_) + (a_row + (mt_) * 16) * LDSZ + (ks_) * 16 + a_kk);                         \
        asm volatile(                                                                         \
            "ldmatrix.sync.aligned.m8n8.x4.shared.b16 {%0,%1,%2,%3}, [%4];\n"                 \
            : "=r"(a[fb_][mt_][0]), "=r"(a[fb_][mt_][1]),                                     \
              "=r"(a[fb_][mt_][2]), "=r"(a[fb_][mt_][3])                                      \
            : "r"(ad_));                                                                      \
    } while (0)

    // single ldmatrix: B fragments 2p_, 2p_+1 of sub-step ks_ into buffer fb_
#define LDSM_B(bs_, ks_, fb_, p_)                                                             \
    do {                                                                                      \
        uint32_t bd_ = (uint32_t)__cvta_generic_to_shared(                                    \
            (bs_) + (b_row + (p_) * 16) * LDSZ + (ks_) * 16 + b_kk);                          \
        asm volatile(                                                                         \
            "ldmatrix.sync.aligned.m8n8.x4.shared.b16 {%0,%1,%2,%3}, [%4];\n"                 \
            : "=r"(b[fb_][2 * (p_)][0]), "=r"(b[fb_][2 * (p_)][1]),                           \
              "=r"(b[fb_][2 * (p_) + 1][0]), "=r"(b[fb_][2 * (p_) + 1][1])                    \
            : "r"(bd_));                                                                      \
    } while (0)

#define MMA1(fb_, mt_, nt_)                                                                   \
    asm volatile(                                                                             \
        "mma.sync.aligned.m16n8k16.row.col.f16.f16.f16.f16 "                                  \
        "{%0,%1}, {%2,%3,%4,%5}, {%6,%7}, {%0,%1};\n"                                         \
        : "+r"(acc[mt_][nt_][0]), "+r"(acc[mt_][nt_][1])                                      \
        : "r"(a[fb_][mt_][0]), "r"(a[fb_][mt_][1]),                                           \
          "r"(a[fb_][mt_][2]), "r"(a[fb_][mt_][3]),                                           \
          "r"(b[fb_][nt_][0]), "r"(b[fb_][nt_][1]))

    // 32 MMAs from buffer fbm_, with next sub-step's 8 LDSM (from asl_/bsl_,
    // sub-step ksl_, into buffer fbm_^1) interleaved one per 4 MMAs.
#define KSTEP(asl_, bsl_, ksl_, fbm_)                                                         \
    do {                                                                                      \
        _Pragma("unroll")                                                                     \
        for (int g_ = 0; g_ < 8; g_++) {                                                      \
            if (g_ < 4) LDSM_A(asl_, ksl_, (fbm_) ^ 1, g_);                                   \
            else        LDSM_B(bsl_, ksl_, (fbm_) ^ 1, g_ - 4);                               \
            _Pragma("unroll")                                                                 \
            for (int i_ = 0; i_ < 4; i_++) {                                                  \
                int m_ = g_ * 4 + i_;                                                         \
                MMA1(fbm_, m_ >> 3, m_ & 7);                                                  \
            }                                                                                 \
        }                                                                                     \
    } while (0)

#define MMA_STEP(fb_)                                                                         \
    do {                                                                                      \
        _Pragma("unroll")                                                                     \
        for (int mt_ = 0; mt_ < 4; mt_++) {                                                   \
            _Pragma("unroll")                                                                 \
            for (int nt_ = 0; nt_ < 8; nt_++) MMA1(fb_, mt_, nt_);                            \
        }                                                                                     \
    } while (0)

    // prologue: stage 0 ready + first fragments preloaded
    ISSUE(0, 0);
    ISSUE(1, 1);
    asm volatile("cp.async.wait_group 1;" ::: "memory");
    __syncthreads();
    {
        const __half* as0 = As;
        const __half* bs0 = Bs;
#pragma unroll
        for (int g = 0; g < 4; g++) LDSM_A(as0, 0, 0, g);
#pragma unroll
        for (int g = 0; g < 4; g++) LDSM_B(bs0, 0, 0, g);
    }

    int st = 0;
    for (int kt = 0; kt < NKT; kt++) {
        if (kt + 2 < NKT) {
            int s2 = (st + 2 >= 3) ? st - 1 : st + 2;
            ISSUE(kt + 2, s2);
        }
        const __half* as = As + st * A_ELE;
        const __half* bs = Bs + st * B_ELE;
        const int stn = (st + 1 == 3) ? 0 : st + 1;

        KSTEP(as, bs, 1, 0);   // mma ks0 (buf0), load ks1 -> buf1
        KSTEP(as, bs, 2, 1);   // mma ks1 (buf1), load ks2 -> buf0
        KSTEP(as, bs, 3, 0);   // mma ks2 (buf0), load ks3 -> buf1
        if (kt + 1 < NKT) {
            if (kt + 2 < NKT)
                asm volatile("cp.async.wait_group 1;" ::: "memory");
            else
                asm volatile("cp.async.wait_group 0;" ::: "memory");
            __syncthreads();
            const __half* asn = As + stn * A_ELE;
            const __half* bsn = Bs + stn * B_ELE;
            KSTEP(asn, bsn, 0, 1);   // mma ks3 (buf1), load next-kt ks0 -> buf0
        } else {
            MMA_STEP(1);             // last kt: plain final batch
        }
        st = stn;
    }

    // ---- epilogue ---------------------------------------------------------
    const bool mirror = (bi != bj);
    const int q = lane & 3;
    const bool qeven = (q & 1) == 0;
    __syncthreads();   // pipe smem reusable

#pragma unroll
    for (int mt = 0; mt < 4; mt++) {
        int rl0 = wm * 64 + mt * 16 + (lane >> 2);
        int rl1 = rl0 + 8;
        int r0 = rowA0 + rl0;
        int r1 = rowA0 + rl1;
        float na0 = g_norms[r0];
        float na1 = g_norms[r1];
#pragma unroll
        for (int nt = 0; nt < 8; nt++) {
            int cl = wn * 64 + nt * 8 + 2 * q;
            int c0 = rowB0 + cl;
            int c1 = c0 + 1;
            float nb0 = nb_s[cl];
            float nb1 = nb_s[cl + 1];

            float2 g0 = __half22float2(*(__half2*)&acc[mt][nt][0]);
            float2 g1 = __half22float2(*(__half2*)&acc[mt][nt][1]);

            float d00 = fmaxf(na0 + nb0 - 2.f * g0.x, 0.f);
            float d01 = fmaxf(na0 + nb1 - 2.f * g0.y, 0.f);
            float d10 = fmaxf(na1 + nb0 - 2.f * g1.x, 0.f);
            float d11 = fmaxf(na1 + nb1 - 2.f * g1.y, 0.f);

            float v00 = (r0 == c0) ? 0.f : nsqrt_approx(d00);
            float v01 = (r0 == c1) ? 0.f : nsqrt_approx(d01);
            float v10 = (r1 == c0) ? 0.f : nsqrt_approx(d10);
            float v11 = (r1 == c1) ? 0.f : nsqrt_approx(d11);

            float x0 = __shfl_xor_sync(0xffffffffu, v00, 1);
            float x1 = __shfl_xor_sync(0xffffffffu, v01, 1);
            float y0 = __shfl_xor_sync(0xffffffffu, v10, 1);
            float y1 = __shfl_xor_sync(0xffffffffu, v11, 1);
            if (qeven) {
                float4 vv = make_float4(v00, v01, x0, x1);
                *(float4*)&out[(size_t)r0 * NROWS + c0] = vv;
            } else {
                float4 vv = make_float4(y0, y1, v10, v11);
                *(float4*)&out[(size_t)r1 * NROWS + (c0 - 2)] = vv;
            }

            if (mirror) {  // transposed staging
                staged[cl * STG_S + rl0]       = v00;
                staged[(cl + 1) * STG_S + rl0] = v01;
                staged[cl * STG_S + rl1]       = v10;
                staged[(cl + 1) * STG_S + rl1] = v11;
            }
        }
    }

    if (mirror) {
        __syncthreads();
#pragma unroll
        for (int i = 0; i < 32; i++) {
            int cl = warp * 32 + i;
            float4 v = *(float4*)&staged[cl * STG_S + lane * 4];
            *(float4*)(out + (size_t)(rowB0 + cl) * NROWS + rowA0 + lane * 4) = v;
        }
    }
#undef ISSUE
#undef LDSM_A
#undef LDSM_B
#undef MMA1
#undef KSTEP
#undef MMA_STEP
}

// ---------------------------------------------------------------------------
extern "C" void kernel_launch(void* const* d_in, const int* in_sizes, int n_in,
                              void* d_out, int out_size) {
    const float* f = (const float*)d_in[0];
    float* out = (float*)d_out;
    (void)in_sizes; (void)n_in; (void)out_size;

    cudaFuncSetAttribute(gemm_kernel, cudaFuncAttributeMaxDynamicSharedMemorySize, SMEM_BYTES);

    prep_kernel<<<NROWS / 16, 512>>>(f);
    gemm_kernel<<<NTILES, 128, SMEM_BYTES>>>(out);
}